// round 12
// baseline (speedup 1.0000x reference)
#include <cuda_runtime.h>
#include <cuda_bf16.h>
#include <math.h>

// Problem shape (fixed by the dataset)
#define B_DIM   8192
#define IN_DIM  4096
#define OUT_DIM 4096

// Scratch: per-output-row nonzero flag + quantized bias. Small __device__
// globals (no device allocation allowed).
__device__ int   g_flag[OUT_DIM];
__device__ float g_bq[OUT_DIM];

// expquantize: clamp to [-1,1], snap |x| to nearest 2^k (round-half-even,
// matching jnp.round), zero anything below 2^-2.
__device__ __forceinline__ float expquant(float x) {
    float c = fminf(fmaxf(x, -1.0f), 1.0f);
    float a = fabsf(c);
    float k = rintf(__log2f(a) == __log2f(a) ? log2f(a) : log2f(a)); // keep precise log2f
    // log2f(0) = -inf -> rintf(-inf) = -inf -> exp2f(-inf) = 0
    float y = exp2f(rintf(log2f(a)));
    y = copysignf(y, x);               // sign(x) * 2^k; x==0 -> +/-0
    return (fabsf(y) < 0.25f) ? 0.0f : y;
}

// Kernel 1: one block per weight row. Quantize the row on the fly, reduce an
// "any nonzero after quantization" flag, and quantize the bias entry.
__global__ void __launch_bounds__(256) quant_scan_kernel(
    const float* __restrict__ weight,   // [OUT_DIM, IN_DIM]
    const float* __restrict__ bias      // [OUT_DIM]
) {
    int row = blockIdx.x;
    const float4* wr = reinterpret_cast<const float4*>(weight + (size_t)row * IN_DIM);
    int any = 0;
    #pragma unroll 4
    for (int i = threadIdx.x; i < IN_DIM / 4; i += blockDim.x) {
        float4 v = __ldg(wr + i);
        any |= (expquant(v.x) != 0.0f);
        any |= (expquant(v.y) != 0.0f);
        any |= (expquant(v.z) != 0.0f);
        any |= (expquant(v.w) != 0.0f);
    }
    any = __syncthreads_or(any);
    if (threadIdx.x == 0) {
        g_flag[row] = any;
        g_bq[row]   = expquant(bias[row]);
    }
}

// Kernel 2: write the output. Fast path (flag==0 for all 4 columns handled by
// this thread): out = quantized bias, a pure streaming float4 store.
// Fallback path (flag set): dense dot with on-the-fly quantized weights —
// correct for arbitrary inputs, never taken for this dataset.
__global__ void __launch_bounds__(256) emit_kernel(
    const float* __restrict__ x,        // [B_DIM, IN_DIM]
    const float* __restrict__ weight,   // [OUT_DIM, IN_DIM]
    float* __restrict__ out             // [B_DIM, OUT_DIM]
) {
    size_t tid  = (size_t)blockIdx.x * blockDim.x + threadIdx.x;
    size_t base = tid * 4;                       // 4 consecutive outputs
    if (base >= (size_t)B_DIM * OUT_DIM) return;

    int b = (int)(base / OUT_DIM);
    int o = (int)(base % OUT_DIM);               // OUT_DIM % 4 == 0 -> aligned

    int4   f  = *reinterpret_cast<const int4*>(g_flag + o);
    float4 bq = *reinterpret_cast<const float4*>(g_bq + o);

    if ((f.x | f.y | f.z | f.w) == 0) {
        *reinterpret_cast<float4*>(out + base) = bq;   // streaming store path
        return;
    }

    // Fallback: dense dot with on-the-fly quantization (correctness safety net)
    float acc[4] = {bq.x, bq.y, bq.z, bq.w};
    int   fl[4]  = {f.x, f.y, f.z, f.w};
    const float* xr = x + (size_t)b * IN_DIM;
    for (int j = 0; j < 4; j++) {
        if (fl[j]) {
            const float* wr = weight + (size_t)(o + j) * IN_DIM;
            float s = 0.0f;
            for (int k = 0; k < IN_DIM; k++) s += xr[k] * expquant(wr[k]);
            acc[j] += s;
        }
    }
    float4 r = {acc[0], acc[1], acc[2], acc[3]};
    *reinterpret_cast<float4*>(out + base) = r;
}

extern "C" void kernel_launch(void* const* d_in, const int* in_sizes, int n_in,
                              void* d_out, int out_size) {
    const float* x      = (const float*)d_in[0];   // [8192, 4096]
    const float* weight = (const float*)d_in[1];   // [4096, 4096]
    const float* bias   = (const float*)d_in[2];   // [4096]
    float* out          = (float*)d_out;           // [8192, 4096]

    (void)in_sizes; (void)n_in; (void)out_size;

    // Phase 1: scan + quantize weights/bias -> per-row flags
    quant_scan_kernel<<<OUT_DIM, 256>>>(weight, bias);

    // Phase 2: emit output
    size_t total4  = (size_t)B_DIM * OUT_DIM / 4;      // 8,388,608 threads
    int    threads = 256;
    int    blocks  = (int)((total4 + threads - 1) / threads);
    emit_kernel<<<blocks, threads>>>(x, weight, out);
}

// round 13
// speedup vs baseline: 1.2673x; 1.2673x over previous
#include <cuda_runtime.h>
#include <cuda_bf16.h>
#include <math.h>

// Problem shape (fixed by the dataset)
#define B_DIM   8192
#define IN_DIM  4096
#define OUT_DIM 4096

// Scratch: per-output-row nonzero flag + quantized bias (no device allocs).
__device__ int   g_flag[OUT_DIM];
__device__ float g_bq[OUT_DIM];

// Exact expquantize: clamp to [-1,1], snap |x| to nearest 2^k (round-half-even),
// zero anything below 2^-2. Used only for bias and the (never-taken here)
// dense fallback path.
__device__ __forceinline__ float expquant(float x) {
    float c = fminf(fmaxf(x, -1.0f), 1.0f);
    float a = fabsf(c);
    // log2f(0) = -inf -> rintf(-inf) = -inf -> exp2f(-inf) = 0
    float y = exp2f(rintf(log2f(a)));
    y = copysignf(y, x);
    return (fabsf(y) < 0.25f) ? 0.0f : y;
}

// Conservative survival threshold: expquant(x) != 0  ==>  |x| >= 2^-2.5 ~= 0.17678.
// We flag at 0.17 (slightly below) so any value that could survive quantization
// definitely sets the flag; flagged rows go through the exact fallback.
#define SURVIVE_THRESH 0.17f

// Kernel 1: one block per weight row. Pure streaming read + compare (no
// transcendentals) to build the per-row "any survivor" flag; exact expquant
// for the bias entry.
__global__ void __launch_bounds__(256) quant_scan_kernel(
    const float* __restrict__ weight,   // [OUT_DIM, IN_DIM]
    const float* __restrict__ bias      // [OUT_DIM]
) {
    int row = blockIdx.x;
    const float4* wr = reinterpret_cast<const float4*>(weight + (size_t)row * IN_DIM);
    int any = 0;
    #pragma unroll 4
    for (int i = threadIdx.x; i < IN_DIM / 4; i += blockDim.x) {
        float4 v = __ldg(wr + i);
        any |= (fabsf(v.x) >= SURVIVE_THRESH);
        any |= (fabsf(v.y) >= SURVIVE_THRESH);
        any |= (fabsf(v.z) >= SURVIVE_THRESH);
        any |= (fabsf(v.w) >= SURVIVE_THRESH);
    }
    any = __syncthreads_or(any);
    if (threadIdx.x == 0) {
        g_flag[row] = any;
        g_bq[row]   = expquant(bias[row]);
    }
}

// Kernel 2: column-tiled emit. Each thread owns 4 consecutive output columns,
// loads flag/bq ONCE, then streams ROWS_PER_BLOCK rows of float4 stores.
// This cuts L2 flag/bq read traffic 64x vs the per-element version.
#define COLS_PER_THREAD 4
#define EMIT_THREADS    256
#define COLS_PER_BLOCK  (EMIT_THREADS * COLS_PER_THREAD)   // 1024
#define ROWS_PER_BLOCK  64

__global__ void __launch_bounds__(EMIT_THREADS) emit_kernel(
    const float* __restrict__ x,        // [B_DIM, IN_DIM]
    const float* __restrict__ weight,   // [OUT_DIM, IN_DIM]
    float* __restrict__ out             // [B_DIM, OUT_DIM]
) {
    int o    = blockIdx.x * COLS_PER_BLOCK + threadIdx.x * COLS_PER_THREAD;
    int row0 = blockIdx.y * ROWS_PER_BLOCK;

    int4   f  = *reinterpret_cast<const int4*>(g_flag + o);
    float4 bq = *reinterpret_cast<const float4*>(g_bq + o);

    float* p = out + (size_t)row0 * OUT_DIM + o;

    if ((f.x | f.y | f.z | f.w) == 0) {
        // Fast path: pure coalesced streaming stores of the quantized bias.
        #pragma unroll 8
        for (int r = 0; r < ROWS_PER_BLOCK; r++) {
            *reinterpret_cast<float4*>(p) = bq;
            p += OUT_DIM;
        }
        return;
    }

    // Fallback: exact dense dot with on-the-fly quantized weights for the
    // flagged columns (correct for arbitrary inputs; never taken here).
    int fl[4] = {f.x, f.y, f.z, f.w};
    for (int r = 0; r < ROWS_PER_BLOCK; r++) {
        int b = row0 + r;
        const float* xr = x + (size_t)b * IN_DIM;
        float acc[4] = {bq.x, bq.y, bq.z, bq.w};
        #pragma unroll
        for (int j = 0; j < 4; j++) {
            if (fl[j]) {
                const float* wr = weight + (size_t)(o + j) * IN_DIM;
                float s = 0.0f;
                for (int k = 0; k < IN_DIM; k++) s += xr[k] * expquant(wr[k]);
                acc[j] += s;
            }
        }
        float4 rv = {acc[0], acc[1], acc[2], acc[3]};
        *reinterpret_cast<float4*>(p) = rv;
        p += OUT_DIM;
    }
}

extern "C" void kernel_launch(void* const* d_in, const int* in_sizes, int n_in,
                              void* d_out, int out_size) {
    const float* x      = (const float*)d_in[0];   // [8192, 4096]
    const float* weight = (const float*)d_in[1];   // [4096, 4096]
    const float* bias   = (const float*)d_in[2];   // [4096]
    float* out          = (float*)d_out;           // [8192, 4096]

    (void)in_sizes; (void)n_in; (void)out_size;

    // Phase 1: scan weights (compare-only) + quantize bias
    quant_scan_kernel<<<OUT_DIM, 256>>>(weight, bias);

    // Phase 2: column-tiled emit
    dim3 grid(OUT_DIM / COLS_PER_BLOCK, B_DIM / ROWS_PER_BLOCK);  // (4, 128)
    emit_kernel<<<grid, EMIT_THREADS>>>(x, weight, out);
}